// round 5
// baseline (speedup 1.0000x reference)
#include <cuda_runtime.h>
#include <math.h>

#define BSZ 2
#define SL  2048
#define DM  1024
#define NH  16
#define HD  64
#define MR  (BSZ * SL)   // 4096 rows

__device__ float g_qkv[(size_t)MR * 3 * DM];  // 48 MB
__device__ float g_o  [(size_t)MR * DM];      // 16 MB

// ---------------------------------------------------------------------------
__device__ __forceinline__ float to_tf32(float x) {
    asm("cvt.rna.tf32.f32 %0, %0;" : "+f"(x));
    return x;
}

__device__ __forceinline__ void mma_tf32(float c[4], const float a0, const float a1,
                                         const float a2, const float a3,
                                         const float b0, const float b1) {
    asm volatile(
        "mma.sync.aligned.m16n8k8.row.col.f32.tf32.tf32.f32 "
        "{%0,%1,%2,%3}, {%4,%5,%6,%7}, {%8,%9}, {%0,%1,%2,%3};"
        : "+f"(c[0]), "+f"(c[1]), "+f"(c[2]), "+f"(c[3])
        : "r"(__float_as_uint(a0)), "r"(__float_as_uint(a1)),
          "r"(__float_as_uint(a2)), "r"(__float_as_uint(a3)),
          "r"(__float_as_uint(b0)), "r"(__float_as_uint(b1)));
}

#define P32(k) ((((k) & 3) * 8) + (((k) >> 2) & 7) + ((k) & 32))

// ---------------------------------------------------------------------------
// TF32 GEMM: C = A @ B. Block 128x128x32, 512 threads (16 warps),
// warp tile 32x32, 2-stage double-buffered smem.
// ---------------------------------------------------------------------------
#define GEMM_SMEM (2 * (128 * 36 + 128 * 36) * 4)

__global__ __launch_bounds__(512) void mma_gemm(
    const float* __restrict__ A, const float* __restrict__ B,
    float* __restrict__ C, int M, int N, int K)
{
    extern __shared__ float gsm[];
    // As[stage][row 128][36], Bs[stage][col 128][36]
    float* AsBase = gsm;
    float* BsBase = gsm + 2 * 128 * 36;

    int tid  = threadIdx.x;
    int lane = tid & 31, warp = tid >> 5;
    int wm = (warp & 3) * 32;
    int wn = (warp >> 2) * 32;
    int bm = blockIdx.y * 128, bn = blockIdx.x * 128;
    int g  = lane >> 2, tg = lane & 3;

    float c[2][4][4];
#pragma unroll
    for (int mt = 0; mt < 2; mt++)
#pragma unroll
        for (int nt = 0; nt < 4; nt++)
#pragma unroll
            for (int i = 0; i < 4; i++) c[mt][nt][i] = 0.f;

    // staging indices
    int ar  = tid >> 3;          // A row (i=1 adds 64)
    int ac4 = tid & 7;           // A k-chunk
    int bkr = tid >> 5;          // B k row (i=1 adds 16)
    int bc4 = tid & 31;          // B col chunk

    float4 rA[2], rB[2];

#define G_LDG(K0)                                                              \
    {                                                                          \
        rA[0] = *(const float4*)(A + (size_t)(bm + ar) * K + (K0) + 4 * ac4);  \
        rA[1] = *(const float4*)(A + (size_t)(bm + ar + 64) * K + (K0) + 4 * ac4); \
        rB[0] = *(const float4*)(B + (size_t)((K0) + bkr) * N + bn + 4 * bc4); \
        rB[1] = *(const float4*)(B + (size_t)((K0) + bkr + 16) * N + bn + 4 * bc4); \
    }

#define G_STS(S)                                                               \
    {                                                                          \
        float* As = AsBase + (S) * 128 * 36;                                   \
        float* Bs = BsBase + (S) * 128 * 36;                                   \
        _Pragma("unroll")                                                      \
        for (int i = 0; i < 2; i++) {                                          \
            int r = ar + 64 * i;                                               \
            As[r * 36 + 0 * 8 + ac4] = to_tf32(rA[i].x);                       \
            As[r * 36 + 1 * 8 + ac4] = to_tf32(rA[i].y);                       \
            As[r * 36 + 2 * 8 + ac4] = to_tf32(rA[i].z);                       \
            As[r * 36 + 3 * 8 + ac4] = to_tf32(rA[i].w);                       \
            int k  = bkr + 16 * i;                                             \
            int pk = (k & 3) * 8 + (k >> 2);                                   \
            Bs[(4 * bc4 + 0) * 36 + pk] = to_tf32(rB[i].x);                    \
            Bs[(4 * bc4 + 1) * 36 + pk] = to_tf32(rB[i].y);                    \
            Bs[(4 * bc4 + 2) * 36 + pk] = to_tf32(rB[i].z);                    \
            Bs[(4 * bc4 + 3) * 36 + pk] = to_tf32(rB[i].w);                    \
        }                                                                      \
    }

    G_LDG(0);
    G_STS(0);
    __syncthreads();

    for (int k0 = 0; k0 < K; k0 += 32) {
        int s = (k0 >> 5) & 1;
        bool more = (k0 + 32 < K);
        if (more) G_LDG(k0 + 32);

        float* As = AsBase + s * 128 * 36;
        float* Bs = BsBase + s * 128 * 36;

        float a[2][16];
#pragma unroll
        for (int mt = 0; mt < 2; mt++) {
            int rl = wm + mt * 16 + g;
            *(float4*)(&a[mt][0])  = *(float4*)(&As[rl * 36 + 8 * tg]);
            *(float4*)(&a[mt][4])  = *(float4*)(&As[rl * 36 + 8 * tg + 4]);
            *(float4*)(&a[mt][8])  = *(float4*)(&As[(rl + 8) * 36 + 8 * tg]);
            *(float4*)(&a[mt][12]) = *(float4*)(&As[(rl + 8) * 36 + 8 * tg + 4]);
        }

#pragma unroll
        for (int j = 0; j < 4; j++) {
#pragma unroll
            for (int nt = 0; nt < 4; nt++) {
                float2 bv = *(float2*)(&Bs[(wn + nt * 8 + g) * 36 + 8 * tg + 2 * j]);
#pragma unroll
                for (int mt = 0; mt < 2; mt++) {
                    mma_tf32(c[mt][nt],
                             a[mt][2 * j], a[mt][8 + 2 * j],
                             a[mt][2 * j + 1], a[mt][8 + 2 * j + 1],
                             bv.x, bv.y);
                }
            }
        }

        if (more) G_STS(s ^ 1);
        __syncthreads();
    }

#pragma unroll
    for (int mt = 0; mt < 2; mt++)
#pragma unroll
        for (int nt = 0; nt < 4; nt++) {
            int row = bm + wm + mt * 16 + g;
            int col = bn + wn + nt * 8 + 2 * tg;
            *(float2*)(C + (size_t)row * N + col) =
                make_float2(c[mt][nt][0], c[mt][nt][1]);
            *(float2*)(C + (size_t)(row + 8) * N + col) =
                make_float2(c[mt][nt][2], c[mt][nt][3]);
        }
}

// ---------------------------------------------------------------------------
// Tensor-core causal attention, 256 thr / 8 warps, q-block 128,
// 2-stage double-buffered K/V staging in both passes.
// ---------------------------------------------------------------------------
#define ATS 68
// sq 128 + skhi 2*64 + sklo 2*64 + sv 2*64 + sp 128 = 640 rows
#define ATTN_SMEM (640 * ATS * 4)

__global__ __launch_bounds__(256) void attn_tc(
    const float* __restrict__ qkv, float* __restrict__ w_out,
    float* __restrict__ o_out)
{
    extern __shared__ float sm[];
    float* sq   = sm;                     // [128][ATS]
    float* skhiB = sq + 128 * ATS;        // [2][64][ATS]
    float* skloB = skhiB + 2 * 64 * ATS;  // [2][64][ATS]
    float* svB   = skloB + 2 * 64 * ATS;  // [2][64][ATS]
    float* sp    = svB + 2 * 64 * ATS;    // [128][ATS]

    int tid  = threadIdx.x;
    int lane = tid & 31, warp = tid >> 5;
    int g = lane >> 2, tg = lane & 3;
    int wm = warp * 16;
    int qt = (gridDim.x - 1) - blockIdx.x;   // heavy-first
    int h = blockIdx.y, b = blockIdx.z;
    int q0 = qt * 128;
    int ktv = 2 * qt + 1;
    const float scale = 0.125f;

    const float* qb = qkv + (size_t)b * SL * 3 * DM + (size_t)h * HD;
    const float* kb = qb + DM;
    const float* vb = qb + 2 * DM;

    int rr  = tid >> 4;   // 0..15 (row base; +16*i)
    int cc4 = tid & 15;   // k-dim chunk
    int pb  = (cc4 & 7) + ((cc4 & 8) << 2);

    // stage Q: 128 rows x 64 dims, tf32, permuted-d
#pragma unroll
    for (int i = 0; i < 8; i++) {
        int r = rr + 16 * i;
        float4 v = *(const float4*)(qb + (size_t)(q0 + r) * (3 * DM) + 4 * cc4);
        sq[r * ATS + pb + 0]  = to_tf32(v.x);
        sq[r * ATS + pb + 8]  = to_tf32(v.y);
        sq[r * ATS + pb + 16] = to_tf32(v.z);
        sq[r * ATS + pb + 24] = to_tf32(v.w);
    }

    float4 rK[4], rV[4];

#define A_LDG_K(KT)                                                            \
    {                                                                          \
        int k0_ = (KT) * 64;                                                   \
        _Pragma("unroll")                                                      \
        for (int i = 0; i < 4; i++)                                            \
            rK[i] = *(const float4*)(kb + (size_t)(k0_ + rr + 16 * i) * (3 * DM) + 4 * cc4); \
    }
#define A_LDG_V(KT)                                                            \
    {                                                                          \
        int k0_ = (KT) * 64;                                                   \
        _Pragma("unroll")                                                      \
        for (int i = 0; i < 4; i++)                                            \
            rV[i] = *(const float4*)(vb + (size_t)(k0_ + rr + 16 * i) * (3 * DM) + 4 * cc4); \
    }
#define A_STS_HI(S)                                                            \
    {                                                                          \
        float* skhi = skhiB + (S) * 64 * ATS;                                  \
        _Pragma("unroll")                                                      \
        for (int i = 0; i < 4; i++) {                                          \
            int r = rr + 16 * i;                                               \
            skhi[r * ATS + pb + 0]  = to_tf32(rK[i].x);                        \
            skhi[r * ATS + pb + 8]  = to_tf32(rK[i].y);                        \
            skhi[r * ATS + pb + 16] = to_tf32(rK[i].z);                        \
            skhi[r * ATS + pb + 24] = to_tf32(rK[i].w);                        \
        }                                                                      \
    }
#define A_STS_FULL(S)                                                          \
    {                                                                          \
        float* skhi = skhiB + (S) * 64 * ATS;                                  \
        float* sklo = skloB + (S) * 64 * ATS;                                  \
        float* sv   = svB   + (S) * 64 * ATS;                                  \
        _Pragma("unroll")                                                      \
        for (int i = 0; i < 4; i++) {                                          \
            int r = rr + 16 * i;                                               \
            float hx = to_tf32(rK[i].x), hy = to_tf32(rK[i].y),                \
                  hz = to_tf32(rK[i].z), hw = to_tf32(rK[i].w);                \
            skhi[r * ATS + pb + 0]  = hx; sklo[r * ATS + pb + 0]  = to_tf32(rK[i].x - hx); \
            skhi[r * ATS + pb + 8]  = hy; sklo[r * ATS + pb + 8]  = to_tf32(rK[i].y - hy); \
            skhi[r * ATS + pb + 16] = hz; sklo[r * ATS + pb + 16] = to_tf32(rK[i].z - hz); \
            skhi[r * ATS + pb + 24] = hw; sklo[r * ATS + pb + 24] = to_tf32(rK[i].w - hw); \
            int pr = P32(r);                                                   \
            sv[(4 * cc4 + 0) * ATS + pr] = to_tf32(rV[i].x);                   \
            sv[(4 * cc4 + 1) * ATS + pr] = to_tf32(rV[i].y);                   \
            sv[(4 * cc4 + 2) * ATS + pr] = to_tf32(rV[i].z);                   \
            sv[(4 * cc4 + 3) * ATS + pr] = to_tf32(rV[i].w);                   \
        }                                                                      \
    }

    float lsum[2] = {0.f, 0.f};

    // ---------------- PASS A: denominators ----------------
    A_LDG_K(0);
    A_STS_HI(0);
    __syncthreads();

    for (int kt = 0; kt <= ktv; kt++) {
        int s = kt & 1;
        bool more = kt < ktv;
        if (more) A_LDG_K(kt + 1);

        float* skhi = skhiB + s * 64 * ATS;
        int k0 = kt * 64;

        float c[8][4];
#pragma unroll
        for (int nt = 0; nt < 8; nt++)
#pragma unroll
            for (int e = 0; e < 4; e++) c[nt][e] = 0.f;

#pragma unroll
        for (int kc = 0; kc < 64; kc += 32) {
            float4 a0 = *(float4*)(&sq[(wm + g) * ATS + kc + 8 * tg]);
            float4 a1 = *(float4*)(&sq[(wm + g) * ATS + kc + 8 * tg + 4]);
            float4 a2 = *(float4*)(&sq[(wm + g + 8) * ATS + kc + 8 * tg]);
            float4 a3 = *(float4*)(&sq[(wm + g + 8) * ATS + kc + 8 * tg + 4]);
            float a[4][4] = {{a0.x, a2.x, a0.y, a2.y}, {a0.z, a2.z, a0.w, a2.w},
                             {a1.x, a3.x, a1.y, a3.y}, {a1.z, a3.z, a1.w, a3.w}};
#pragma unroll
            for (int j = 0; j < 4; j++)
#pragma unroll
                for (int nt = 0; nt < 8; nt++) {
                    float2 bv = *(float2*)(&skhi[(nt * 8 + g) * ATS + kc + 8 * tg + 2 * j]);
                    mma_tf32(c[nt], a[j][0], a[j][1], a[j][2], a[j][3], bv.x, bv.y);
                }
        }

#pragma unroll
        for (int nt = 0; nt < 8; nt++)
#pragma unroll
            for (int e = 0; e < 4; e++) {
                int col = k0 + nt * 8 + 2 * tg + (e & 1);
                int row = q0 + wm + g + ((e >> 1) << 3);
                if (col <= row) lsum[e >> 1] += __expf(c[nt][e] * scale);
            }

        if (more) A_STS_HI(s ^ 1);
        __syncthreads();
    }

    lsum[0] += __shfl_xor_sync(0xffffffffu, lsum[0], 1);
    lsum[0] += __shfl_xor_sync(0xffffffffu, lsum[0], 2);
    lsum[1] += __shfl_xor_sync(0xffffffffu, lsum[1], 1);
    lsum[1] += __shfl_xor_sync(0xffffffffu, lsum[1], 2);
    float inv_l[2] = {1.f / lsum[0], 1.f / lsum[1]};

    float o[8][4];
#pragma unroll
    for (int nt = 0; nt < 8; nt++)
#pragma unroll
        for (int e = 0; e < 4; e++) o[nt][e] = 0.f;

    float* wbase = w_out + ((size_t)(b * NH + h) * SL + q0) * SL;

    // ---------------- PASS B: w + o ----------------
    A_LDG_K(0); A_LDG_V(0);
    A_STS_FULL(0);
    __syncthreads();

    for (int kt = 0; kt <= ktv; kt++) {
        int s = kt & 1;
        bool more = kt < ktv;
        if (more) { A_LDG_K(kt + 1); A_LDG_V(kt + 1); }

        float* skhi = skhiB + s * 64 * ATS;
        float* sklo = skloB + s * 64 * ATS;
        float* sv   = svB   + s * 64 * ATS;
        int k0 = kt * 64;

        float c[8][4];
#pragma unroll
        for (int nt = 0; nt < 8; nt++)
#pragma unroll
            for (int e = 0; e < 4; e++) c[nt][e] = 0.f;

#pragma unroll
        for (int kc = 0; kc < 64; kc += 32) {
            float4 a0 = *(float4*)(&sq[(wm + g) * ATS + kc + 8 * tg]);
            float4 a1 = *(float4*)(&sq[(wm + g) * ATS + kc + 8 * tg + 4]);
            float4 a2 = *(float4*)(&sq[(wm + g + 8) * ATS + kc + 8 * tg]);
            float4 a3 = *(float4*)(&sq[(wm + g + 8) * ATS + kc + 8 * tg + 4]);
            float a[4][4] = {{a0.x, a2.x, a0.y, a2.y}, {a0.z, a2.z, a0.w, a2.w},
                             {a1.x, a3.x, a1.y, a3.y}, {a1.z, a3.z, a1.w, a3.w}};
#pragma unroll
            for (int j = 0; j < 4; j++)
#pragma unroll
                for (int nt = 0; nt < 8; nt++) {
                    float2 bh = *(float2*)(&skhi[(nt * 8 + g) * ATS + kc + 8 * tg + 2 * j]);
                    mma_tf32(c[nt], a[j][0], a[j][1], a[j][2], a[j][3], bh.x, bh.y);
                    float2 bl = *(float2*)(&sklo[(nt * 8 + g) * ATS + kc + 8 * tg + 2 * j]);
                    mma_tf32(c[nt], a[j][0], a[j][1], a[j][2], a[j][3], bl.x, bl.y);
                }
        }

#pragma unroll
        for (int nt = 0; nt < 8; nt++) {
            float p[4];
#pragma unroll
            for (int e = 0; e < 4; e++) {
                int col = k0 + nt * 8 + 2 * tg + (e & 1);
                int row = q0 + wm + g + ((e >> 1) << 3);
                p[e] = (col <= row) ? __expf(c[nt][e] * scale) * inv_l[e >> 1] : 0.f;
            }
            int colb = nt * 8 + 2 * tg;
            *(float2*)(wbase + (size_t)(wm + g) * SL + k0 + colb) =
                make_float2(p[0], p[1]);
            *(float2*)(wbase + (size_t)(wm + g + 8) * SL + k0 + colb) =
                make_float2(p[2], p[3]);
            int pc0 = P32(colb), pc1 = P32(colb + 1);
            sp[(wm + g) * ATS + pc0]     = to_tf32(p[0]);
            sp[(wm + g) * ATS + pc1]     = to_tf32(p[1]);
            sp[(wm + g + 8) * ATS + pc0] = to_tf32(p[2]);
            sp[(wm + g + 8) * ATS + pc1] = to_tf32(p[3]);
        }
        __syncwarp();

        // o += P @ V
#pragma unroll
        for (int kc = 0; kc < 64; kc += 32) {
            float4 a0 = *(float4*)(&sp[(wm + g) * ATS + kc + 8 * tg]);
            float4 a1 = *(float4*)(&sp[(wm + g) * ATS + kc + 8 * tg + 4]);
            float4 a2 = *(float4*)(&sp[(wm + g + 8) * ATS + kc + 8 * tg]);
            float4 a3 = *(float4*)(&sp[(wm + g + 8) * ATS + kc + 8 * tg + 4]);
            float a[4][4] = {{a0.x, a2.x, a0.y, a2.y}, {a0.z, a2.z, a0.w, a2.w},
                             {a1.x, a3.x, a1.y, a3.y}, {a1.z, a3.z, a1.w, a3.w}};
#pragma unroll
            for (int j = 0; j < 4; j++)
#pragma unroll
                for (int nt = 0; nt < 8; nt++) {
                    float2 bv = *(float2*)(&sv[(nt * 8 + g) * ATS + kc + 8 * tg + 2 * j]);
                    mma_tf32(o[nt], a[j][0], a[j][1], a[j][2], a[j][3], bv.x, bv.y);
                }
        }

        if (more) A_STS_FULL(s ^ 1);
        __syncthreads();
    }

    // zero the never-touched upper region
    int zstart = (ktv + 1) * 64;
    float4 z = make_float4(0.f, 0.f, 0.f, 0.f);
    for (int r = warp; r < 128; r += 8)
        for (int cc = zstart + lane * 4; cc < SL; cc += 128)
            *(float4*)(wbase + (size_t)r * SL + cc) = z;

    // write o (normalized) in (b, s, h*d) layout
#pragma unroll
    for (int nt = 0; nt < 8; nt++) {
        int cold = nt * 8 + 2 * tg;
        size_t r0o = (size_t)((size_t)b * SL + q0 + wm + g) * DM + h * HD + cold;
        size_t r1o = (size_t)((size_t)b * SL + q0 + wm + g + 8) * DM + h * HD + cold;
        *(float2*)(o_out + r0o) = make_float2(o[nt][0], o[nt][1]);
        *(float2*)(o_out + r1o) = make_float2(o[nt][2], o[nt][3]);
    }
}

// ---------------------------------------------------------------------------
extern "C" void kernel_launch(void* const* d_in, const int* in_sizes, int n_in,
                              void* d_out, int out_size)
{
    const float* x      = (const float*)d_in[0];
    const float* w_qkv  = (const float*)d_in[1];
    const float* w_proj = (const float*)d_in[2];
    float* out    = (float*)d_out;
    float* w_attn = out + (size_t)MR * DM;

    float *qkvp, *op;
    cudaGetSymbolAddress((void**)&qkvp, g_qkv);
    cudaGetSymbolAddress((void**)&op,   g_o);

    cudaFuncSetAttribute(mma_gemm,
                         cudaFuncAttributeMaxDynamicSharedMemorySize,
                         GEMM_SMEM);
    cudaFuncSetAttribute(attn_tc,
                         cudaFuncAttributeMaxDynamicSharedMemorySize,
                         ATTN_SMEM);

    // 1) qkv = x @ w_qkv
    dim3 g1(3 * DM / 128, MR / 128);
    mma_gemm<<<g1, 512, GEMM_SMEM>>>(x, w_qkv, qkvp, MR, 3 * DM, DM);

    // 2) attention
    dim3 g2(SL / 128, NH, BSZ);
    attn_tc<<<g2, 256, ATTN_SMEM>>>(qkvp, w_attn, op);

    // 3) out = o @ w_proj
    dim3 g3(DM / 128, MR / 128);
    mma_gemm<<<g3, 512, GEMM_SMEM>>>(op, w_proj, out, MR, DM, DM);
}

// round 7
// speedup vs baseline: 1.2165x; 1.2165x over previous
#include <cuda_runtime.h>
#include <cuda_bf16.h>
#include <math.h>
#include <stdint.h>

#define BSZ 2
#define SL  2048
#define DM  1024
#define NH  16
#define HD  64
#define MR  (BSZ * SL)   // 4096 rows

__device__ float g_qkv[(size_t)MR * 3 * DM];   // 48 MB
__device__ float g_o  [(size_t)MR * DM];       // 16 MB
__device__ float g_l  [(size_t)BSZ * NH * SL]; // softmax denominators

// ---------------------------------------------------------------------------
__device__ __forceinline__ float to_tf32(float x) {
    asm("cvt.rna.tf32.f32 %0, %0;" : "+f"(x));
    return x;
}

__device__ __forceinline__ void mma_tf32(float c[4], const float a0, const float a1,
                                         const float a2, const float a3,
                                         const float b0, const float b1) {
    asm volatile(
        "mma.sync.aligned.m16n8k8.row.col.f32.tf32.tf32.f32 "
        "{%0,%1,%2,%3}, {%4,%5,%6,%7}, {%8,%9}, {%0,%1,%2,%3};"
        : "+f"(c[0]), "+f"(c[1]), "+f"(c[2]), "+f"(c[3])
        : "r"(__float_as_uint(a0)), "r"(__float_as_uint(a1)),
          "r"(__float_as_uint(a2)), "r"(__float_as_uint(a3)),
          "r"(__float_as_uint(b0)), "r"(__float_as_uint(b1)));
}

// bf16 m16n8k16: a = {(r,klo),(r+8,klo),(r,khi),(r+8,khi)}, b = {klo,khi}
__device__ __forceinline__ void mma_bf16(float c[4], uint32_t a0, uint32_t a1,
                                         uint32_t a2, uint32_t a3,
                                         uint32_t b0, uint32_t b1) {
    asm volatile(
        "mma.sync.aligned.m16n8k16.row.col.f32.bf16.bf16.f32 "
        "{%0,%1,%2,%3}, {%4,%5,%6,%7}, {%8,%9}, {%0,%1,%2,%3};"
        : "+f"(c[0]), "+f"(c[1]), "+f"(c[2]), "+f"(c[3])
        : "r"(a0), "r"(a1), "r"(a2), "r"(a3), "r"(b0), "r"(b1));
}

__device__ __forceinline__ uint32_t pack_bf16(float a, float b) {
    __nv_bfloat162 t = __floats2bfloat162_rn(a, b);
    return *(uint32_t*)&t;
}

#define P32(k) ((((k) & 3) * 8) + (((k) >> 2) & 7) + ((k) & 32))
// pair-position permutation within a 16-wide d block (pairs j=0..7)
#define PPOS(j) ((((j) & 3) << 1) | (((j) & 7) >> 2))

// ---------------------------------------------------------------------------
// TF32 tensor-core GEMM: C[M,N] = A[M,K] @ B[K,N], row-major.
// Block 128x128x32, 256 thr, warp tile 32x64. R3 structure, but inner loop is
// nt-outer / j-inner with B fetched as 2x LDS.128 per nt (1 load -> 8 MMAs).
// ---------------------------------------------------------------------------
#define GBM 128
#define GBN 128
#define GBK 32

__global__ __launch_bounds__(256) void mma_gemm(
    const float* __restrict__ A, const float* __restrict__ B,
    float* __restrict__ C, int M, int N, int K)
{
    __shared__ float As[GBM][36];
    __shared__ float Bs[GBN][36];

    int tid  = threadIdx.x;
    int lane = tid & 31, warp = tid >> 5;
    int wm = (warp & 3) * 32;
    int wn = (warp >> 2) * 64;
    int bm = blockIdx.y * GBM, bn = blockIdx.x * GBN;
    int g  = lane >> 2, tg = lane & 3;

    float c[2][8][4];
#pragma unroll
    for (int mt = 0; mt < 2; mt++)
#pragma unroll
        for (int nt = 0; nt < 8; nt++)
#pragma unroll
            for (int i = 0; i < 4; i++) c[mt][nt][i] = 0.f;

    int ar  = tid >> 3;
    int ac4 = tid & 7;
    int bk  = tid & 7;
    int bn4 = tid >> 3;

    float4 rA[4], rB[4];
#pragma unroll
    for (int i = 0; i < 4; i++) {
        rA[i] = *(const float4*)(A + (size_t)(bm + ar + 32 * i) * K + 4 * ac4);
        rB[i] = *(const float4*)(B + (size_t)(bk + 8 * i) * N + bn + 4 * bn4);
    }

    for (int k0 = 0; k0 < K; k0 += GBK) {
#pragma unroll
        for (int i = 0; i < 4; i++) {
            int r = ar + 32 * i;
            As[r][0 * 8 + ac4] = to_tf32(rA[i].x);
            As[r][1 * 8 + ac4] = to_tf32(rA[i].y);
            As[r][2 * 8 + ac4] = to_tf32(rA[i].z);
            As[r][3 * 8 + ac4] = to_tf32(rA[i].w);
            int k  = bk + 8 * i;
            int pk = (k & 3) * 8 + (k >> 2);
            Bs[4 * bn4 + 0][pk] = to_tf32(rB[i].x);
            Bs[4 * bn4 + 1][pk] = to_tf32(rB[i].y);
            Bs[4 * bn4 + 2][pk] = to_tf32(rB[i].z);
            Bs[4 * bn4 + 3][pk] = to_tf32(rB[i].w);
        }
        __syncthreads();

        if (k0 + GBK < K) {
#pragma unroll
            for (int i = 0; i < 4; i++) {
                rA[i] = *(const float4*)(A + (size_t)(bm + ar + 32 * i) * K +
                                         k0 + GBK + 4 * ac4);
                rB[i] = *(const float4*)(B + (size_t)(k0 + GBK + bk + 8 * i) * N +
                                         bn + 4 * bn4);
            }
        }

        float a[2][16];
#pragma unroll
        for (int mt = 0; mt < 2; mt++) {
            int rl = wm + mt * 16 + g;
            *(float4*)(&a[mt][0])  = *(float4*)(&As[rl][8 * tg]);
            *(float4*)(&a[mt][4])  = *(float4*)(&As[rl][8 * tg + 4]);
            *(float4*)(&a[mt][8])  = *(float4*)(&As[rl + 8][8 * tg]);
            *(float4*)(&a[mt][12]) = *(float4*)(&As[rl + 8][8 * tg + 4]);
        }

#pragma unroll
        for (int nt = 0; nt < 8; nt++) {
            float4 b0 = *(float4*)(&Bs[wn + nt * 8 + g][8 * tg]);
            float4 b1 = *(float4*)(&Bs[wn + nt * 8 + g][8 * tg + 4]);
#pragma unroll
            for (int mt = 0; mt < 2; mt++) {
                mma_tf32(c[mt][nt], a[mt][0], a[mt][8],  a[mt][1], a[mt][9],
                         b0.x, b0.y);
                mma_tf32(c[mt][nt], a[mt][2], a[mt][10], a[mt][3], a[mt][11],
                         b0.z, b0.w);
                mma_tf32(c[mt][nt], a[mt][4], a[mt][12], a[mt][5], a[mt][13],
                         b1.x, b1.y);
                mma_tf32(c[mt][nt], a[mt][6], a[mt][14], a[mt][7], a[mt][15],
                         b1.z, b1.w);
            }
        }
        __syncthreads();
    }

#pragma unroll
    for (int mt = 0; mt < 2; mt++)
#pragma unroll
        for (int nt = 0; nt < 8; nt++) {
            int row = bm + wm + mt * 16 + g;
            int col = bn + wn + nt * 8 + 2 * tg;
            *(float2*)(C + (size_t)row * N + col) =
                make_float2(c[mt][nt][0], c[mt][nt][1]);
            *(float2*)(C + (size_t)(row + 8) * N + col) =
                make_float2(c[mt][nt][2], c[mt][nt][3]);
        }
}

// ---------------------------------------------------------------------------
// Single-pass causal attention. Block = (b, h, 128 q-rows), 256 thr, 8 warps.
// QK = bf16 split (Qhi*Khi + Qhi*Klo + Qlo*Khi), m16n8k16. PV = tf32.
// Writes UNNORMALIZED exp to w_out, stores per-row l; o scaled by 1/l here.
// ---------------------------------------------------------------------------
// byte offsets in dynamic smem
#define QHI_OFF 0                    // u32[128*40]  (bf16 pairs, 160B rows)
#define QLO_OFF 20480
#define KHI_OFF 40960                // u32[64*40]
#define KLO_OFF 51200
#define SV_OFF  61440                // float[64*68]
#define SP_OFF  78848                // float[128*68]
#define ATTN_SMEM 113664
#define BTS 40                       // bf16 row stride in u32

__global__ __launch_bounds__(256) void attn_sp(
    const float* __restrict__ qkv, float* __restrict__ w_out,
    float* __restrict__ o_out, float* __restrict__ l_out)
{
    extern __shared__ char smc[];
    uint32_t* sqhi = (uint32_t*)(smc + QHI_OFF);
    uint32_t* sqlo = (uint32_t*)(smc + QLO_OFF);
    uint32_t* skhi = (uint32_t*)(smc + KHI_OFF);
    uint32_t* sklo = (uint32_t*)(smc + KLO_OFF);
    float*    sv   = (float*)(smc + SV_OFF);
    float*    sp   = (float*)(smc + SP_OFF);

    int tid  = threadIdx.x;
    int lane = tid & 31, warp = tid >> 5;
    int g = lane >> 2, tg = lane & 3;
    int wm = warp * 16;
    int qt = (gridDim.x - 1) - blockIdx.x;     // heavy-first
    int h = blockIdx.y, b = blockIdx.z;
    int q0 = qt * 128;
    int ktv = 2 * qt + 1;
    const float scale = 0.125f;

    const float* qb = qkv + (size_t)b * SL * 3 * DM + (size_t)h * HD;
    const float* kb = qb + DM;
    const float* vb = qb + 2 * DM;

    // ---- stage Q hi/lo (128 rows x 64 d), permuted-pair bf16 layout ----
#pragma unroll
    for (int i = 0; i < 8; i++) {
        int idx = tid + i * 256;
        int r = idx >> 4, c4 = idx & 15;
        float4 v = *(const float4*)(qb + (size_t)(q0 + r) * (3 * DM) + 4 * c4);
        int blk = c4 >> 2;
        int j0 = (2 * c4) & 7, j1 = (2 * c4 + 1) & 7;
        int s0 = r * BTS + blk * 8 + PPOS(j0);
        int s1 = r * BTS + blk * 8 + PPOS(j1);
        float hx = __bfloat162float(__float2bfloat16(v.x));
        float hy = __bfloat162float(__float2bfloat16(v.y));
        float hz = __bfloat162float(__float2bfloat16(v.z));
        float hw = __bfloat162float(__float2bfloat16(v.w));
        sqhi[s0] = pack_bf16(v.x, v.y);
        sqhi[s1] = pack_bf16(v.z, v.w);
        sqlo[s0] = pack_bf16(v.x - hx, v.y - hy);
        sqlo[s1] = pack_bf16(v.z - hz, v.w - hw);
    }

    float lsum[2] = {0.f, 0.f};
    float o[8][4];
#pragma unroll
    for (int nt = 0; nt < 8; nt++)
#pragma unroll
        for (int e = 0; e < 4; e++) o[nt][e] = 0.f;

    float* wbase = w_out + ((size_t)(b * NH + h) * SL + q0) * SL;

    for (int kt = 0; kt <= ktv; kt++) {
        int k0 = kt * 64;
        __syncthreads();
        // ---- stage K hi/lo (bf16 perm) + V (tf32, [d][perm key]) ----
#pragma unroll
        for (int i = 0; i < 4; i++) {
            int idx = tid + i * 256;
            int r = idx >> 4, c4 = idx & 15;
            float4 v = *(const float4*)(kb + (size_t)(k0 + r) * (3 * DM) + 4 * c4);
            int blk = c4 >> 2;
            int j0 = (2 * c4) & 7, j1 = (2 * c4 + 1) & 7;
            int s0 = r * BTS + blk * 8 + PPOS(j0);
            int s1 = r * BTS + blk * 8 + PPOS(j1);
            float hx = __bfloat162float(__float2bfloat16(v.x));
            float hy = __bfloat162float(__float2bfloat16(v.y));
            float hz = __bfloat162float(__float2bfloat16(v.z));
            float hw = __bfloat162float(__float2bfloat16(v.w));
            skhi[s0] = pack_bf16(v.x, v.y);
            skhi[s1] = pack_bf16(v.z, v.w);
            sklo[s0] = pack_bf16(v.x - hx, v.y - hy);
            sklo[s1] = pack_bf16(v.z - hz, v.w - hw);
            float4 vv = *(const float4*)(vb + (size_t)(k0 + r) * (3 * DM) + 4 * c4);
            int pr = P32(r);
            sv[(4 * c4 + 0) * 68 + pr] = to_tf32(vv.x);
            sv[(4 * c4 + 1) * 68 + pr] = to_tf32(vv.y);
            sv[(4 * c4 + 2) * 68 + pr] = to_tf32(vv.z);
            sv[(4 * c4 + 3) * 68 + pr] = to_tf32(vv.w);
        }
        __syncthreads();

        // ---- S = Q K^T via bf16 split (3 mma per 16-d chunk per 8-col tile)
        float c[8][4];
#pragma unroll
        for (int nt = 0; nt < 8; nt++)
#pragma unroll
            for (int e = 0; e < 4; e++) c[nt][e] = 0.f;

#pragma unroll
        for (int kc = 0; kc < 4; kc++) {
            uint2 ah0 = *(uint2*)(sqhi + (wm + g) * BTS + kc * 8 + 2 * tg);
            uint2 ah1 = *(uint2*)(sqhi + (wm + g + 8) * BTS + kc * 8 + 2 * tg);
            uint2 al0 = *(uint2*)(sqlo + (wm + g) * BTS + kc * 8 + 2 * tg);
            uint2 al1 = *(uint2*)(sqlo + (wm + g + 8) * BTS + kc * 8 + 2 * tg);
#pragma unroll
            for (int nt = 0; nt < 8; nt++) {
                uint2 bh = *(uint2*)(skhi + (nt * 8 + g) * BTS + kc * 8 + 2 * tg);
                uint2 bl = *(uint2*)(sklo + (nt * 8 + g) * BTS + kc * 8 + 2 * tg);
                mma_bf16(c[nt], ah0.x, ah1.x, ah0.y, ah1.y, bh.x, bh.y);
                mma_bf16(c[nt], ah0.x, ah1.x, ah0.y, ah1.y, bl.x, bl.y);
                mma_bf16(c[nt], al0.x, al1.x, al0.y, al1.y, bh.x, bh.y);
            }
        }

        // ---- exp (unnormalized), write w, accumulate l, stage P ----
#pragma unroll
        for (int nt = 0; nt < 8; nt++) {
            float p[4];
#pragma unroll
            for (int e = 0; e < 4; e++) {
                int col = k0 + nt * 8 + 2 * tg + (e & 1);
                int row = q0 + wm + g + ((e >> 1) << 3);
                p[e] = (col <= row) ? __expf(c[nt][e] * scale) : 0.f;
                lsum[e >> 1] += p[e];
            }
            int colb = nt * 8 + 2 * tg;
            *(float2*)(wbase + (size_t)(wm + g) * SL + k0 + colb) =
                make_float2(p[0], p[1]);
            *(float2*)(wbase + (size_t)(wm + g + 8) * SL + k0 + colb) =
                make_float2(p[2], p[3]);
            int pc0 = P32(colb), pc1 = P32(colb + 1);
            sp[(wm + g) * 68 + pc0]     = to_tf32(p[0]);
            sp[(wm + g) * 68 + pc1]     = to_tf32(p[1]);
            sp[(wm + g + 8) * 68 + pc0] = to_tf32(p[2]);
            sp[(wm + g + 8) * 68 + pc1] = to_tf32(p[3]);
        }
        __syncwarp();

        // ---- o += P @ V (tf32) ----
#pragma unroll
        for (int kc = 0; kc < 64; kc += 32) {
            float4 a0 = *(float4*)(&sp[(wm + g) * 68 + kc + 8 * tg]);
            float4 a1 = *(float4*)(&sp[(wm + g) * 68 + kc + 8 * tg + 4]);
            float4 a2 = *(float4*)(&sp[(wm + g + 8) * 68 + kc + 8 * tg]);
            float4 a3 = *(float4*)(&sp[(wm + g + 8) * 68 + kc + 8 * tg + 4]);
            float a[4][4] = {{a0.x, a2.x, a0.y, a2.y}, {a0.z, a2.z, a0.w, a2.w},
                             {a1.x, a3.x, a1.y, a3.y}, {a1.z, a3.z, a1.w, a3.w}};
#pragma unroll
            for (int j = 0; j < 4; j++)
#pragma unroll
                for (int nt = 0; nt < 8; nt++) {
                    float2 bv = *(float2*)(&sv[(nt * 8 + g) * 68 + kc + 8 * tg + 2 * j]);
                    mma_tf32(o[nt], a[j][0], a[j][1], a[j][2], a[j][3], bv.x, bv.y);
                }
        }
    }

    // zero the never-touched upper region
    int zstart = (ktv + 1) * 64;
    float4 z = make_float4(0.f, 0.f, 0.f, 0.f);
    for (int r = warp; r < 128; r += 8)
        for (int cc = zstart + lane * 4; cc < SL; cc += 128)
            *(float4*)(wbase + (size_t)r * SL + cc) = z;

    // reduce l across tg lanes
    lsum[0] += __shfl_xor_sync(0xffffffffu, lsum[0], 1);
    lsum[0] += __shfl_xor_sync(0xffffffffu, lsum[0], 2);
    lsum[1] += __shfl_xor_sync(0xffffffffu, lsum[1], 1);
    lsum[1] += __shfl_xor_sync(0xffffffffu, lsum[1], 2);
    float inv_l[2] = {1.f / lsum[0], 1.f / lsum[1]};

    if (tg == 0) {
        size_t lb = (size_t)(b * NH + h) * SL + q0;
        l_out[lb + wm + g]     = lsum[0];
        l_out[lb + wm + g + 8] = lsum[1];
    }

    // write o (scaled by 1/l) in (b, s, h*d) layout
#pragma unroll
    for (int nt = 0; nt < 8; nt++) {
        int cold = nt * 8 + 2 * tg;
        size_t r0o = (size_t)((size_t)b * SL + q0 + wm + g) * DM + h * HD + cold;
        size_t r1o = (size_t)((size_t)b * SL + q0 + wm + g + 8) * DM + h * HD + cold;
        *(float2*)(o_out + r0o) = make_float2(o[nt][0] * inv_l[0],
                                              o[nt][1] * inv_l[0]);
        *(float2*)(o_out + r1o) = make_float2(o[nt][2] * inv_l[1],
                                              o[nt][3] * inv_l[1]);
    }
}

// ---------------------------------------------------------------------------
// Normalize w rows by 1/l — only the written (lower-triangular) tile region.
// ---------------------------------------------------------------------------
__global__ __launch_bounds__(128) void norm_kernel(
    float* __restrict__ w, const float* __restrict__ l)
{
    int row = blockIdx.x;                 // bh*SL + q
    int q = row & (SL - 1);
    float inv = 1.f / l[row];
    int ncols = ((q >> 6) + 1) << 6;      // written region
    float* wr = w + (size_t)row * SL;
    for (int c = threadIdx.x * 4; c < ncols; c += blockDim.x * 4) {
        float4 v = *(float4*)(wr + c);
        v.x *= inv; v.y *= inv; v.z *= inv; v.w *= inv;
        *(float4*)(wr + c) = v;
    }
}

// ---------------------------------------------------------------------------
extern "C" void kernel_launch(void* const* d_in, const int* in_sizes, int n_in,
                              void* d_out, int out_size)
{
    const float* x      = (const float*)d_in[0];  // (2,2048,1024)
    const float* w_qkv  = (const float*)d_in[1];  // (1024,3072)
    const float* w_proj = (const float*)d_in[2];  // (1024,1024)
    float* out    = (float*)d_out;                 // (2,2048,1024)
    float* w_attn = out + (size_t)MR * DM;         // (2,16,2048,2048)

    float *qkvp, *op, *lp;
    cudaGetSymbolAddress((void**)&qkvp, g_qkv);
    cudaGetSymbolAddress((void**)&op,   g_o);
    cudaGetSymbolAddress((void**)&lp,   g_l);

    cudaFuncSetAttribute(attn_sp,
                         cudaFuncAttributeMaxDynamicSharedMemorySize, ATTN_SMEM);

    // 1) qkv = x @ w_qkv  (tf32 mma.sync)
    dim3 g1(3 * DM / GBN, MR / GBM);
    mma_gemm<<<g1, 256>>>(x, w_qkv, qkvp, MR, 3 * DM, DM);

    // 2) single-pass attention (unnormalized w + l, o scaled)
    dim3 g2(SL / 128, NH, BSZ);
    attn_sp<<<g2, 256, ATTN_SMEM>>>(qkvp, w_attn, op, lp);

    // 3) normalize w rows
    norm_kernel<<<BSZ * NH * SL, 128>>>(w_attn, lp);

    // 4) out = o @ w_proj  (tf32 mma.sync)
    dim3 g3(DM / GBN, MR / GBM);
    mma_gemm<<<g3, 256>>>(op, w_proj, out, MR, DM, DM);
}

// round 9
// speedup vs baseline: 1.4923x; 1.2268x over previous
#include <cuda_runtime.h>
#include <cuda_bf16.h>
#include <math.h>
#include <stdint.h>

#define BSZ 2
#define SL  2048
#define DM  1024
#define NH  16
#define HD  64
#define MR  (BSZ * SL)   // 4096 rows

__device__ float g_qkv[(size_t)MR * 3 * DM];   // 48 MB
__device__ float g_o  [(size_t)MR * DM];       // 16 MB (tf32-rounded o)
__device__ float g_xr [(size_t)MR * DM];       // 16 MB (tf32-rounded x)
__device__ float g_wT [(size_t)3 * DM * DM + (size_t)DM * DM]; // rounded, transposed weights
__device__ float g_l  [(size_t)BSZ * NH * SL]; // softmax denominators

// ---------------------------------------------------------------------------
__device__ __forceinline__ float to_tf32(float x) {
    asm("cvt.rna.tf32.f32 %0, %0;" : "+f"(x));
    return x;
}

__device__ __forceinline__ void mma_tf32(float c[4], const float a0, const float a1,
                                         const float a2, const float a3,
                                         const float b0, const float b1) {
    asm volatile(
        "mma.sync.aligned.m16n8k8.row.col.f32.tf32.tf32.f32 "
        "{%0,%1,%2,%3}, {%4,%5,%6,%7}, {%8,%9}, {%0,%1,%2,%3};"
        : "+f"(c[0]), "+f"(c[1]), "+f"(c[2]), "+f"(c[3])
        : "r"(__float_as_uint(a0)), "r"(__float_as_uint(a1)),
          "r"(__float_as_uint(a2)), "r"(__float_as_uint(a3)),
          "r"(__float_as_uint(b0)), "r"(__float_as_uint(b1)));
}

__device__ __forceinline__ void mma_bf16(float c[4], uint32_t a0, uint32_t a1,
                                         uint32_t a2, uint32_t a3,
                                         uint32_t b0, uint32_t b1) {
    asm volatile(
        "mma.sync.aligned.m16n8k16.row.col.f32.bf16.bf16.f32 "
        "{%0,%1,%2,%3}, {%4,%5,%6,%7}, {%8,%9}, {%0,%1,%2,%3};"
        : "+f"(c[0]), "+f"(c[1]), "+f"(c[2]), "+f"(c[3])
        : "r"(a0), "r"(a1), "r"(a2), "r"(a3), "r"(b0), "r"(b1));
}

__device__ __forceinline__ uint32_t pack_bf16(float a, float b) {
    __nv_bfloat162 t = __floats2bfloat162_rn(a, b);
    return *(uint32_t*)&t;
}

__device__ __forceinline__ uint32_t smem_u32(const void* p) {
    uint32_t a;
    asm("{ .reg .u64 t; cvta.to.shared.u64 t, %1; cvt.u32.u64 %0, t; }"
        : "=r"(a) : "l"(p));
    return a;
}

__device__ __forceinline__ void cp_async16(uint32_t dst, const void* src) {
    asm volatile("cp.async.ca.shared.global [%0], [%1], 16;"
                 :: "r"(dst), "l"(src));
}
__device__ __forceinline__ void cp_commit() {
    asm volatile("cp.async.commit_group;");
}
template <int N>
__device__ __forceinline__ void cp_wait() {
    asm volatile("cp.async.wait_group %0;" :: "n"(N));
}

#define P32(k) ((((k) & 3) * 8) + (((k) >> 2) & 7) + ((k) & 32))
#define PPOS(j) ((((j) & 3) << 1) | (((j) & 7) >> 2))

// ---------------------------------------------------------------------------
// prep kernels: round x to tf32; round + transpose weights to [N][K]
// ---------------------------------------------------------------------------
__global__ __launch_bounds__(256) void round_tf32_kernel(
    const float* __restrict__ src, float* __restrict__ dst, int n4)
{
    int i = blockIdx.x * 256 + threadIdx.x;
    if (i < n4) {
        float4 v = *(const float4*)(src + 4 * (size_t)i);
        v.x = to_tf32(v.x); v.y = to_tf32(v.y);
        v.z = to_tf32(v.z); v.w = to_tf32(v.w);
        *(float4*)(dst + 4 * (size_t)i) = v;
    }
}

__global__ __launch_bounds__(256) void transpose_round32(
    const float* __restrict__ src, float* __restrict__ dst, int R, int Cc)
{
    __shared__ float t[32][33];
    int r0 = blockIdx.y * 32, c0 = blockIdx.x * 32;
    int tx = threadIdx.x, ty = threadIdx.y;
#pragma unroll
    for (int j = 0; j < 32; j += 8)
        t[ty + j][tx] = to_tf32(src[(size_t)(r0 + ty + j) * Cc + c0 + tx]);
    __syncthreads();
#pragma unroll
    for (int j = 0; j < 32; j += 8)
        dst[(size_t)(c0 + ty + j) * R + r0 + tx] = t[tx][ty + j];
}

// ---------------------------------------------------------------------------
// TF32 GEMM v2: C[M,N] = A[M,K] @ Bt[N,K]^T.  Inputs MUST be tf32-pre-rounded.
// Block 128(M) x 256(N), BK=32, 256 thr / 8 warps, warp tile 64x64.
// cp.async double-buffered smem, unpermuted [row][40] layout, per-j LDS.64.
// ---------------------------------------------------------------------------
#define GS_A (128 * 40)          // floats per A stage
#define GS_B (256 * 40)
#define GS_STAGE (GS_A + GS_B)
#define GEMM2_SMEM (2 * GS_STAGE * 4)

__global__ __launch_bounds__(256) void mma_gemm2(
    const float* __restrict__ A, const float* __restrict__ Bt,
    float* __restrict__ C, int M, int N, int K)
{
    extern __shared__ float gsm[];
    uint32_t sb = smem_u32(gsm);

    int tid  = threadIdx.x;
    int lane = tid & 31, warp = tid >> 5;
    int g = lane >> 2, tg = lane & 3;
    int wm = (warp & 1) * 64;        // warp m-offset (2 warps in M)
    int wn = (warp >> 1) * 64;       // warp n-offset (4 warps in N)
    int bm = blockIdx.y * 128, bn = blockIdx.x * 256;

    float c[4][8][4];
#pragma unroll
    for (int mt = 0; mt < 4; mt++)
#pragma unroll
        for (int nt = 0; nt < 8; nt++)
#pragma unroll
            for (int i = 0; i < 4; i++) c[mt][nt][i] = 0.f;

#define G2_ISSUE(S, K0)                                                        \
    {                                                                          \
        uint32_t abase = sb + (S) * GS_STAGE * 4;                              \
        uint32_t bbase = abase + GS_A * 4;                                     \
        _Pragma("unroll")                                                      \
        for (int i = 0; i < 4; i++) {                                          \
            int id = tid + 256 * i;                                            \
            int r = id >> 3, k4 = id & 7;                                      \
            cp_async16(abase + r * 160 + k4 * 16,                              \
                       A + (size_t)(bm + r) * K + (K0) + 4 * k4);              \
        }                                                                      \
        _Pragma("unroll")                                                      \
        for (int i = 0; i < 8; i++) {                                          \
            int id = tid + 256 * i;                                            \
            int n = id >> 3, k4 = id & 7;                                      \
            cp_async16(bbase + n * 160 + k4 * 16,                              \
                       Bt + (size_t)(bn + n) * K + (K0) + 4 * k4);             \
        }                                                                      \
        cp_commit();                                                           \
    }

    G2_ISSUE(0, 0);

    int nch = K / 32;
    for (int ch = 0; ch < nch; ch++) {
        int s = ch & 1;
        if (ch + 1 < nch) {
            G2_ISSUE(s ^ 1, (ch + 1) * 32);
            cp_wait<1>();
        } else {
            cp_wait<0>();
        }
        __syncthreads();

        const float* As = gsm + s * GS_STAGE;
        const float* Bs = As + GS_A;

#pragma unroll
        for (int j = 0; j < 4; j++) {
            int kc = 8 * j + 2 * tg;
            // A fragments: 4 mt x 2 row-groups, float2 each
            float2 af[4][2];
#pragma unroll
            for (int mt = 0; mt < 4; mt++) {
                int rl = wm + mt * 16 + g;
                af[mt][0] = *(const float2*)(As + rl * 40 + kc);
                af[mt][1] = *(const float2*)(As + (rl + 8) * 40 + kc);
            }
#pragma unroll
            for (int nt = 0; nt < 8; nt++) {
                float2 bf = *(const float2*)(Bs + (wn + nt * 8 + g) * 40 + kc);
#pragma unroll
                for (int mt = 0; mt < 4; mt++)
                    mma_tf32(c[mt][nt], af[mt][0].x, af[mt][1].x,
                             af[mt][0].y, af[mt][1].y, bf.x, bf.y);
            }
        }
        __syncthreads();
    }

#pragma unroll
    for (int mt = 0; mt < 4; mt++)
#pragma unroll
        for (int nt = 0; nt < 8; nt++) {
            int row = bm + wm + mt * 16 + g;
            int col = bn + wn + nt * 8 + 2 * tg;
            *(float2*)(C + (size_t)row * N + col) =
                make_float2(c[mt][nt][0], c[mt][nt][1]);
            *(float2*)(C + (size_t)(row + 8) * N + col) =
                make_float2(c[mt][nt][2], c[mt][nt][3]);
        }
}

// ---------------------------------------------------------------------------
// Single-pass causal attention (Round-7 version; o written tf32-pre-rounded
// so the cp.async proj GEMM can consume it without a rounding pass).
// ---------------------------------------------------------------------------
#define QHI_OFF 0
#define QLO_OFF 20480
#define KHI_OFF 40960
#define KLO_OFF 51200
#define SV_OFF  61440
#define SP_OFF  78848
#define ATTN_SMEM 113664
#define BTS 40

__global__ __launch_bounds__(256) void attn_sp(
    const float* __restrict__ qkv, float* __restrict__ w_out,
    float* __restrict__ o_out, float* __restrict__ l_out)
{
    extern __shared__ char smc[];
    uint32_t* sqhi = (uint32_t*)(smc + QHI_OFF);
    uint32_t* sqlo = (uint32_t*)(smc + QLO_OFF);
    uint32_t* skhi = (uint32_t*)(smc + KHI_OFF);
    uint32_t* sklo = (uint32_t*)(smc + KLO_OFF);
    float*    sv   = (float*)(smc + SV_OFF);
    float*    sp   = (float*)(smc + SP_OFF);

    int tid  = threadIdx.x;
    int lane = tid & 31, warp = tid >> 5;
    int g = lane >> 2, tg = lane & 3;
    int wm = warp * 16;
    int qt = (gridDim.x - 1) - blockIdx.x;     // heavy-first
    int h = blockIdx.y, b = blockIdx.z;
    int q0 = qt * 128;
    int ktv = 2 * qt + 1;
    const float scale = 0.125f;

    const float* qb = qkv + (size_t)b * SL * 3 * DM + (size_t)h * HD;
    const float* kb = qb + DM;
    const float* vb = qb + 2 * DM;

#pragma unroll
    for (int i = 0; i < 8; i++) {
        int idx = tid + i * 256;
        int r = idx >> 4, c4 = idx & 15;
        float4 v = *(const float4*)(qb + (size_t)(q0 + r) * (3 * DM) + 4 * c4);
        int blk = c4 >> 2;
        int j0 = (2 * c4) & 7, j1 = (2 * c4 + 1) & 7;
        int s0 = r * BTS + blk * 8 + PPOS(j0);
        int s1 = r * BTS + blk * 8 + PPOS(j1);
        float hx = __bfloat162float(__float2bfloat16(v.x));
        float hy = __bfloat162float(__float2bfloat16(v.y));
        float hz = __bfloat162float(__float2bfloat16(v.z));
        float hw = __bfloat162float(__float2bfloat16(v.w));
        sqhi[s0] = pack_bf16(v.x, v.y);
        sqhi[s1] = pack_bf16(v.z, v.w);
        sqlo[s0] = pack_bf16(v.x - hx, v.y - hy);
        sqlo[s1] = pack_bf16(v.z - hz, v.w - hw);
    }

    float lsum[2] = {0.f, 0.f};
    float o[8][4];
#pragma unroll
    for (int nt = 0; nt < 8; nt++)
#pragma unroll
        for (int e = 0; e < 4; e++) o[nt][e] = 0.f;

    float* wbase = w_out + ((size_t)(b * NH + h) * SL + q0) * SL;

    for (int kt = 0; kt <= ktv; kt++) {
        int k0 = kt * 64;
        __syncthreads();
#pragma unroll
        for (int i = 0; i < 4; i++) {
            int idx = tid + i * 256;
            int r = idx >> 4, c4 = idx & 15;
            float4 v = *(const float4*)(kb + (size_t)(k0 + r) * (3 * DM) + 4 * c4);
            int blk = c4 >> 2;
            int j0 = (2 * c4) & 7, j1 = (2 * c4 + 1) & 7;
            int s0 = r * BTS + blk * 8 + PPOS(j0);
            int s1 = r * BTS + blk * 8 + PPOS(j1);
            float hx = __bfloat162float(__float2bfloat16(v.x));
            float hy = __bfloat162float(__float2bfloat16(v.y));
            float hz = __bfloat162float(__float2bfloat16(v.z));
            float hw = __bfloat162float(__float2bfloat16(v.w));
            skhi[s0] = pack_bf16(v.x, v.y);
            skhi[s1] = pack_bf16(v.z, v.w);
            sklo[s0] = pack_bf16(v.x - hx, v.y - hy);
            sklo[s1] = pack_bf16(v.z - hz, v.w - hw);
            float4 vv = *(const float4*)(vb + (size_t)(k0 + r) * (3 * DM) + 4 * c4);
            int pr = P32(r);
            sv[(4 * c4 + 0) * 68 + pr] = to_tf32(vv.x);
            sv[(4 * c4 + 1) * 68 + pr] = to_tf32(vv.y);
            sv[(4 * c4 + 2) * 68 + pr] = to_tf32(vv.z);
            sv[(4 * c4 + 3) * 68 + pr] = to_tf32(vv.w);
        }
        __syncthreads();

        float c[8][4];
#pragma unroll
        for (int nt = 0; nt < 8; nt++)
#pragma unroll
            for (int e = 0; e < 4; e++) c[nt][e] = 0.f;

#pragma unroll
        for (int kc = 0; kc < 4; kc++) {
            uint2 ah0 = *(uint2*)(sqhi + (wm + g) * BTS + kc * 8 + 2 * tg);
            uint2 ah1 = *(uint2*)(sqhi + (wm + g + 8) * BTS + kc * 8 + 2 * tg);
            uint2 al0 = *(uint2*)(sqlo + (wm + g) * BTS + kc * 8 + 2 * tg);
            uint2 al1 = *(uint2*)(sqlo + (wm + g + 8) * BTS + kc * 8 + 2 * tg);
#pragma unroll
            for (int nt = 0; nt < 8; nt++) {
                uint2 bh = *(uint2*)(skhi + (nt * 8 + g) * BTS + kc * 8 + 2 * tg);
                uint2 bl = *(uint2*)(sklo + (nt * 8 + g) * BTS + kc * 8 + 2 * tg);
                mma_bf16(c[nt], ah0.x, ah1.x, ah0.y, ah1.y, bh.x, bh.y);
                mma_bf16(c[nt], ah0.x, ah1.x, ah0.y, ah1.y, bl.x, bl.y);
                mma_bf16(c[nt], al0.x, al1.x, al0.y, al1.y, bh.x, bh.y);
            }
        }

#pragma unroll
        for (int nt = 0; nt < 8; nt++) {
            float p[4];
#pragma unroll
            for (int e = 0; e < 4; e++) {
                int col = k0 + nt * 8 + 2 * tg + (e & 1);
                int row = q0 + wm + g + ((e >> 1) << 3);
                p[e] = (col <= row) ? __expf(c[nt][e] * scale) : 0.f;
                lsum[e >> 1] += p[e];
            }
            int colb = nt * 8 + 2 * tg;
            *(float2*)(wbase + (size_t)(wm + g) * SL + k0 + colb) =
                make_float2(p[0], p[1]);
            *(float2*)(wbase + (size_t)(wm + g + 8) * SL + k0 + colb) =
                make_float2(p[2], p[3]);
            int pc0 = P32(colb), pc1 = P32(colb + 1);
            sp[(wm + g) * 68 + pc0]     = to_tf32(p[0]);
            sp[(wm + g) * 68 + pc1]     = to_tf32(p[1]);
            sp[(wm + g + 8) * 68 + pc0] = to_tf32(p[2]);
            sp[(wm + g + 8) * 68 + pc1] = to_tf32(p[3]);
        }
        __syncwarp();

#pragma unroll
        for (int kc = 0; kc < 64; kc += 32) {
            float4 a0 = *(float4*)(&sp[(wm + g) * 68 + kc + 8 * tg]);
            float4 a1 = *(float4*)(&sp[(wm + g) * 68 + kc + 8 * tg + 4]);
            float4 a2 = *(float4*)(&sp[(wm + g + 8) * 68 + kc + 8 * tg]);
            float4 a3 = *(float4*)(&sp[(wm + g + 8) * 68 + kc + 8 * tg + 4]);
            float a[4][4] = {{a0.x, a2.x, a0.y, a2.y}, {a0.z, a2.z, a0.w, a2.w},
                             {a1.x, a3.x, a1.y, a3.y}, {a1.z, a3.z, a1.w, a3.w}};
#pragma unroll
            for (int j = 0; j < 4; j++)
#pragma unroll
                for (int nt = 0; nt < 8; nt++) {
                    float2 bv = *(float2*)(&sv[(nt * 8 + g) * 68 + kc + 8 * tg + 2 * j]);
                    mma_tf32(o[nt], a[j][0], a[j][1], a[j][2], a[j][3], bv.x, bv.y);
                }
        }
    }

    int zstart = (ktv + 1) * 64;
    float4 z = make_float4(0.f, 0.f, 0.f, 0.f);
    for (int r = warp; r < 128; r += 8)
        for (int cc = zstart + lane * 4; cc < SL; cc += 128)
            *(float4*)(wbase + (size_t)r * SL + cc) = z;

    lsum[0] += __shfl_xor_sync(0xffffffffu, lsum[0], 1);
    lsum[0] += __shfl_xor_sync(0xffffffffu, lsum[0], 2);
    lsum[1] += __shfl_xor_sync(0xffffffffu, lsum[1], 1);
    lsum[1] += __shfl_xor_sync(0xffffffffu, lsum[1], 2);
    float inv_l[2] = {1.f / lsum[0], 1.f / lsum[1]};

    if (tg == 0) {
        size_t lb = (size_t)(b * NH + h) * SL + q0;
        l_out[lb + wm + g]     = lsum[0];
        l_out[lb + wm + g + 8] = lsum[1];
    }

    // write o scaled by 1/l, tf32-pre-rounded (proj GEMM reads it raw)
#pragma unroll
    for (int nt = 0; nt < 8; nt++) {
        int cold = nt * 8 + 2 * tg;
        size_t r0o = (size_t)((size_t)b * SL + q0 + wm + g) * DM + h * HD + cold;
        size_t r1o = (size_t)((size_t)b * SL + q0 + wm + g + 8) * DM + h * HD + cold;
        *(float2*)(o_out + r0o) = make_float2(to_tf32(o[nt][0] * inv_l[0]),
                                              to_tf32(o[nt][1] * inv_l[0]));
        *(float2*)(o_out + r1o) = make_float2(to_tf32(o[nt][2] * inv_l[1]),
                                              to_tf32(o[nt][3] * inv_l[1]));
    }
}

// ---------------------------------------------------------------------------
__global__ __launch_bounds__(128) void norm_kernel(
    float* __restrict__ w, const float* __restrict__ l)
{
    int row = blockIdx.x;
    int q = row & (SL - 1);
    float inv = 1.f / l[row];
    int ncols = ((q >> 6) + 1) << 6;
    float* wr = w + (size_t)row * SL;
    for (int c = threadIdx.x * 4; c < ncols; c += blockDim.x * 4) {
        float4 v = *(float4*)(wr + c);
        v.x *= inv; v.y *= inv; v.z *= inv; v.w *= inv;
        *(float4*)(wr + c) = v;
    }
}

// ---------------------------------------------------------------------------
extern "C" void kernel_launch(void* const* d_in, const int* in_sizes, int n_in,
                              void* d_out, int out_size)
{
    const float* x      = (const float*)d_in[0];  // (2,2048,1024)
    const float* w_qkv  = (const float*)d_in[1];  // (1024,3072)
    const float* w_proj = (const float*)d_in[2];  // (1024,1024)
    float* out    = (float*)d_out;                 // (2,2048,1024)
    float* w_attn = out + (size_t)MR * DM;         // (2,16,2048,2048)

    float *qkvp, *op, *xr, *wT, *lp;
    cudaGetSymbolAddress((void**)&qkvp, g_qkv);
    cudaGetSymbolAddress((void**)&op,   g_o);
    cudaGetSymbolAddress((void**)&xr,   g_xr);
    cudaGetSymbolAddress((void**)&wT,   g_wT);
    cudaGetSymbolAddress((void**)&lp,   g_l);
    float* wprojT = wT + (size_t)3 * DM * DM;

    cudaFuncSetAttribute(mma_gemm2,
                         cudaFuncAttributeMaxDynamicSharedMemorySize, GEMM2_SMEM);
    cudaFuncSetAttribute(attn_sp,
                         cudaFuncAttributeMaxDynamicSharedMemorySize, ATTN_SMEM);

    // 0) prep: round x; round+transpose weights
    round_tf32_kernel<<<(MR * DM / 4 + 255) / 256, 256>>>(x, xr, MR * DM / 4);
    transpose_round32<<<dim3(3 * DM / 32, DM / 32), dim3(32, 8)>>>(w_qkv, wT, DM, 3 * DM);
    transpose_round32<<<dim3(DM / 32, DM / 32), dim3(32, 8)>>>(w_proj, wprojT, DM, DM);

    // 1) qkv = x @ w_qkv
    dim3 g1(3 * DM / 256, MR / 128);
    mma_gemm2<<<g1, 256, GEMM2_SMEM>>>(xr, wT, qkvp, MR, 3 * DM, DM);

    // 2) single-pass attention
    dim3 g2(SL / 128, NH, BSZ);
    attn_sp<<<g2, 256, ATTN_SMEM>>>(qkvp, w_attn, op, lp);

    // 3) normalize w rows
    norm_kernel<<<BSZ * NH * SL, 128>>>(w_attn, lp);

    // 4) out = o @ w_proj
    dim3 g3(DM / 256, MR / 128);
    mma_gemm2<<<g3, 256, GEMM2_SMEM>>>(op, wprojT, out, MR, DM, DM);
}